// round 15
// baseline (speedup 1.0000x reference)
#include <cuda_runtime.h>
#include <cstdint>

#define NQ      18
#define QDIM    262144          // 2^18
#define QMASK   (QDIM - 1)
#define XN      73728           // 4096 * 18
#define TWODIM  (2 * QDIM)

// ---------------- device scratch (no allocations allowed) ----------------
__device__ float2 g_gates[54 * 4];   // [layer*18+q][4] = U00,U01,U10,U11
__device__ float2 g_xc[XN];
__device__ float2 g_svA[QDIM];
__device__ float2 g_svB[QDIM];
__device__ float  g_acc[132];        // [0..63] dec hidden, [64..127] val hidden, [128] xnorm2, [129] svnorm2
__device__ float  g_part[1024 * 128];

__device__ __forceinline__ float2 cmul(float2 a, float2 b) {
    return make_float2(a.x * b.x - a.y * b.y, a.x * b.y + a.y * b.x);
}
__device__ __forceinline__ float2 cadd(float2 a, float2 b) {
    return make_float2(a.x + b.x, a.y + b.y);
}

// ---------------- setup: fused gate matrices + zero accumulators ----------------
__global__ void setup_kernel(const float* __restrict__ qp) {
    int t = threadIdx.x;
    if (t < 132) g_acc[t] = 0.f;
    if (t < 54) {
        float a = qp[t * 3 + 0] * 0.5f;
        float b = qp[t * 3 + 1] * 0.5f;
        float c = qp[t * 3 + 2] * 0.5f;
        float ca = cosf(a), sa = sinf(a);
        float cb = cosf(b), sb = sinf(b);
        float cc = cosf(c), sc = sinf(c);
        // Ry*Rx
        float2 m00 = make_float2( cb * ca,  sb * sa);
        float2 m01 = make_float2(-sb * ca, -cb * sa);
        float2 m10 = make_float2( sb * ca, -cb * sa);
        float2 m11 = make_float2( cb * ca, -sb * sa);
        float2 em = make_float2(cc, -sc);   // e^{-ic/2}
        float2 ep = make_float2(cc,  sc);   // e^{+ic/2}
        g_gates[t * 4 + 0] = cmul(em, m00);
        g_gates[t * 4 + 1] = cmul(em, m01);
        g_gates[t * 4 + 2] = cmul(ep, m10);
        g_gates[t * 4 + 3] = cmul(ep, m11);
    }
}

// ---------------- encoder: 128 blocks x 32 rows, W1 + state in smem ----------------
// sm layout (floats): stile[32*256] | w1s[256*64] | hid[32*64] | w2s[64*36] | encs[32*36] | red[256]
#define ENC_SMEM_FLOATS (8192 + 16384 + 2048 + 2304 + 1152 + 256)
__global__ void encoder_kernel(const float* __restrict__ state,
                               const float* __restrict__ w1,
                               const float* __restrict__ b1,
                               const float* __restrict__ w2,
                               const float* __restrict__ b2) {
    extern __shared__ float sm[];
    float* stile = sm;
    float* w1s   = sm + 8192;
    float* hid   = sm + 24576;
    float* w2s   = sm + 26624;
    float* encs  = sm + 28928;
    float* red   = sm + 30080;
    int t = threadIdx.x;
    int R0 = blockIdx.x * 32;

    for (int i = t; i < 8192; i += 256)  stile[i] = state[R0 * 256 + i];
    for (int i = t; i < 16384; i += 256) w1s[i] = w1[i];
    for (int i = t; i < 2304; i += 256)  w2s[i] = w2[i];
    __syncthreads();

    int rg = t >> 4, cq = t & 15;
    int r0 = rg * 2, c0 = cq * 4;
    float a00 = 0, a01 = 0, a02 = 0, a03 = 0, a10 = 0, a11 = 0, a12 = 0, a13 = 0;
    const float* s0p = stile + r0 * 256;
    const float* s1p = stile + (r0 + 1) * 256;
#pragma unroll 4
    for (int k = 0; k < 256; k++) {
        float4 w = *(const float4*)&w1s[k * 64 + c0];
        float s0 = s0p[k], s1 = s1p[k];
        a00 += s0 * w.x; a01 += s0 * w.y; a02 += s0 * w.z; a03 += s0 * w.w;
        a10 += s1 * w.x; a11 += s1 * w.y; a12 += s1 * w.z; a13 += s1 * w.w;
    }
    float bv0 = b1[c0], bv1 = b1[c0 + 1], bv2 = b1[c0 + 2], bv3 = b1[c0 + 3];
    hid[r0 * 64 + c0 + 0] = fmaxf(a00 + bv0, 0.f);
    hid[r0 * 64 + c0 + 1] = fmaxf(a01 + bv1, 0.f);
    hid[r0 * 64 + c0 + 2] = fmaxf(a02 + bv2, 0.f);
    hid[r0 * 64 + c0 + 3] = fmaxf(a03 + bv3, 0.f);
    hid[(r0 + 1) * 64 + c0 + 0] = fmaxf(a10 + bv0, 0.f);
    hid[(r0 + 1) * 64 + c0 + 1] = fmaxf(a11 + bv1, 0.f);
    hid[(r0 + 1) * 64 + c0 + 2] = fmaxf(a12 + bv2, 0.f);
    hid[(r0 + 1) * 64 + c0 + 3] = fmaxf(a13 + bv3, 0.f);
    __syncthreads();

    for (int idx = t; idx < 32 * 36; idx += 256) {
        int r = idx / 36, j = idx % 36;
        float acc = b2[j];
        const float* hrow = hid + r * 64;
#pragma unroll 8
        for (int k = 0; k < 64; k++) acc += hrow[k] * w2s[k * 36 + j];
        encs[idx] = acc;
    }
    __syncthreads();

    float loc = 0.f;
    for (int idx = t; idx < 32 * 18; idx += 256) {
        int r = idx / 18, q = idx % 18;
        float amp = encs[r * 36 + q];
        float ph  = encs[r * 36 + 18 + q];
        float sn, cs;
        sincosf(ph, &sn, &cs);
        g_xc[(R0 + r) * 18 + q] = make_float2(amp * cs, amp * sn);
        loc += amp * amp;
    }
    red[t] = loc;
    __syncthreads();
    for (int s = 128; s > 0; s >>= 1) { if (t < s) red[t] += red[t + s]; __syncthreads(); }
    if (t == 0) atomicAdd(&g_acc[128], red[0]);
}

// ---------------- layer 0 on |0>: product state, fused with CNOT perm ----------------
__global__ void p1_kernel() {
    __shared__ float2 u[36];   // u[q*2+bit] = column-0 entries of layer-0 gates
    int t = threadIdx.x;
    if (t < 36) {
        int q = t >> 1, bit = t & 1;
        u[t] = g_gates[q * 4 + (bit ? 2 : 0)];
    }
    __syncthreads();
    int b = blockIdx.x;
#pragma unroll 2
    for (int k = 0; k < 4; k++) {
        int y = b * 1024 + k * 256 + t;
        unsigned g = (unsigned)((y ^ (y << 1)) & QMASK);
        float2 p = u[((g >> 17) & 1)];
#pragma unroll
        for (int q = 1; q < 18; q++) {
            float2 w = u[q * 2 + ((g >> (17 - q)) & 1)];
            p = cmul(p, w);
        }
        g_svA[y] = p;
    }
}

// ---------------- 12 gates on bits 0..11 (qubits 17..6) in 32KB smem chunks ----------------
__global__ void low_kernel(int layer, int gather) {
    __shared__ float2 ch[4096];
    __shared__ float2 sg[48];
    int t = threadIdx.x, b = blockIdx.x;   // 64 blocks x 512 threads
    if (t < 48) {
        int beta = t >> 2, e = t & 3;
        sg[t] = g_gates[(layer * 18 + (17 - beta)) * 4 + e];
    }
    int base = b << 12;
#pragma unroll
    for (int k = 0; k < 8; k++) {
        int i = k * 512 + t;
        int idx = base + i;
        int s = gather ? ((idx ^ (idx << 1)) & QMASK) : idx;
        ch[i] = g_svA[s];
    }
    __syncthreads();
    for (int beta = 0; beta < 12; beta++) {
        float2 u00 = sg[beta * 4 + 0], u01 = sg[beta * 4 + 1];
        float2 u10 = sg[beta * 4 + 2], u11 = sg[beta * 4 + 3];
        int stride = 1 << beta;
#pragma unroll
        for (int k = 0; k < 4; k++) {
            int p = k * 512 + t;
            int i0 = ((p >> beta) << (beta + 1)) | (p & (stride - 1));
            int i1 = i0 | stride;
            float2 v0 = ch[i0], v1 = ch[i1];
            ch[i0] = cadd(cmul(u00, v0), cmul(u01, v1));
            ch[i1] = cadd(cmul(u10, v0), cmul(u11, v1));
        }
        __syncthreads();
    }
#pragma unroll
    for (int k = 0; k < 8; k++) {
        int i = k * 512 + t;
        g_svB[base + i] = ch[i];
    }
}

// ---------------- 6 gates on bits 12..17 (qubits 5..0), strided chunks ----------------
__global__ void high_kernel(int layer) {
    __shared__ float2 ch[4096];
    __shared__ float2 sg[24];
    int t = threadIdx.x, b = blockIdx.x;   // 64 blocks (mid bits 6..11) x 512 threads
    if (t < 24) {
        int g = t >> 2, e = t & 3;
        sg[t] = g_gates[(layer * 18 + (5 - g)) * 4 + e];
    }
#pragma unroll
    for (int k = 0; k < 8; k++) {
        int l = k * 512 + t;
        int hi = l >> 6, lo = l & 63;
        ch[l] = g_svB[(hi << 12) | (b << 6) | lo];
    }
    __syncthreads();
    for (int g = 0; g < 6; g++) {
        int beta = 6 + g;   // local bit
        float2 u00 = sg[g * 4 + 0], u01 = sg[g * 4 + 1];
        float2 u10 = sg[g * 4 + 2], u11 = sg[g * 4 + 3];
        int stride = 1 << beta;
#pragma unroll
        for (int k = 0; k < 4; k++) {
            int p = k * 512 + t;
            int i0 = ((p >> beta) << (beta + 1)) | (p & (stride - 1));
            int i1 = i0 | stride;
            float2 v0 = ch[i0], v1 = ch[i1];
            ch[i0] = cadd(cmul(u00, v0), cmul(u01, v1));
            ch[i1] = cadd(cmul(u10, v0), cmul(u11, v1));
        }
        __syncthreads();
    }
#pragma unroll
    for (int k = 0; k < 8; k++) {
        int l = k * 512 + t;
        int hi = l >> 6, lo = l & 63;
        g_svA[(hi << 12) | (b << 6) | lo] = ch[l];
    }
}

// ---------------- epilogue: final perm + add normalized x + state norm ----------------
__global__ void e2_kernel() {
    int t = threadIdx.x, b = blockIdx.x;
    float xn2 = g_acc[128];
    float rs = xn2 > 0.f ? rsqrtf(xn2) : 0.f;
    float loc = 0.f;
#pragma unroll
    for (int k = 0; k < 4; k++) {
        int y = b * 1024 + k * 256 + t;
        int gidx = (y ^ (y << 1)) & QMASK;
        float2 v = g_svA[gidx];
        if (y < XN) {
            float2 x = g_xc[y];
            v.x += x.x * rs;
            v.y += x.y * rs;
        }
        g_svB[y] = v;
        loc += v.x * v.x + v.y * v.y;
    }
    __shared__ float red[256];
    red[t] = loc;
    __syncthreads();
    for (int s = 128; s > 0; s >>= 1) { if (t < s) red[t] += red[t + s]; __syncthreads(); }
    if (t == 0) atomicAdd(&g_acc[129], red[0]);
}

// ---------------- the big GEMV: cl (524288) x [dec_w1 | val_w1] (524288 x 64 each) ----------------
__global__ void gemv_kernel(const float* __restrict__ Wd, const float* __restrict__ Wv) {
    __shared__ float cls[512];
    __shared__ float sred[256 * 8];
    int t = threadIdx.x, b = blockIdx.x;   // 1024 blocks x 256 threads, 512 rows each
    int j0 = b * 512;
    for (int i = t; i < 512; i += 256) {
        int j = j0 + i;
        cls[i] = (j < QDIM) ? g_svB[j].x : g_svB[j - QDIM].y;
    }
    __syncthreads();
    int rg = t >> 4, cq = t & 15;
    float ad0 = 0, ad1 = 0, ad2 = 0, ad3 = 0;
    float av0 = 0, av1 = 0, av2 = 0, av3 = 0;
#pragma unroll 8
    for (int it = 0; it < 32; it++) {
        int jl = it * 16 + rg;
        float c = cls[jl];
        size_t off = (size_t)(j0 + jl) * 64 + (cq << 2);
        float4 d = __ldg((const float4*)(Wd + off));
        float4 v = __ldg((const float4*)(Wv + off));
        ad0 += c * d.x; ad1 += c * d.y; ad2 += c * d.z; ad3 += c * d.w;
        av0 += c * v.x; av1 += c * v.y; av2 += c * v.z; av3 += c * v.w;
    }
    float* sp = &sred[t * 8];
    sp[0] = ad0; sp[1] = ad1; sp[2] = ad2; sp[3] = ad3;
    sp[4] = av0; sp[5] = av1; sp[6] = av2; sp[7] = av3;
    __syncthreads();
    if (t < 128) {
        int isval = t >> 6;
        int c = t & 63;
        int quad = c >> 2;
        int lane = (c & 3) + isval * 4;
        float s = 0.f;
#pragma unroll
        for (int g = 0; g < 16; g++) s += sred[(g * 16 + quad) * 8 + lane];
        g_part[b * 128 + t] = s;
    }
}

// ---------------- final: reduce partials, normalize, MLP heads ----------------
__global__ void final_kernel(const float* __restrict__ db1, const float* __restrict__ dw2,
                             const float* __restrict__ db2, const float* __restrict__ vb1,
                             const float* __restrict__ vw2, const float* __restrict__ vb2,
                             float* __restrict__ out, int out_size) {
    __shared__ float part[1024];
    __shared__ float S[128];
    __shared__ float hd[64], hv[64];
    int t = threadIdx.x;                  // 1024 threads
    int o = t & 127, chunk = t >> 7;      // 8 chunks of 128 partial-blocks
    float s = 0.f;
    for (int i = chunk * 128; i < (chunk + 1) * 128; i++) s += g_part[i * 128 + o];
    part[t] = s;
    __syncthreads();
    if (t < 128) {
        float s2 = 0.f;
#pragma unroll
        for (int c2 = 0; c2 < 8; c2++) s2 += part[c2 * 128 + t];
        S[t] = s2;
    }
    __syncthreads();
    float inv = rsqrtf(g_acc[129]);
    if (t < 64) {
        hd[t] = fmaxf(S[t] * inv + db1[t], 0.f);
        hv[t] = fmaxf(S[64 + t] * inv + vb1[t], 0.f);
    }
    __syncthreads();
    if (t < 18 && t < out_size) {
        float acc = db2[t];
#pragma unroll 8
        for (int k = 0; k < 64; k++) acc += hd[k] * dw2[k * 18 + t];
        out[t] = acc;
    }
    if (t == 32 && out_size > 18) {
        float acc = vb2[0];
#pragma unroll 8
        for (int k = 0; k < 64; k++) acc += hv[k] * vw2[k];
        out[18] = acc;
    }
}

// ---------------- launch ----------------
extern "C" void kernel_launch(void* const* d_in, const int* in_sizes, int n_in,
                              void* d_out, int out_size) {
    const float* state   = (const float*)d_in[0];
    const float* enc_w1  = (const float*)d_in[1];
    const float* enc_b1  = (const float*)d_in[2];
    const float* enc_w2  = (const float*)d_in[3];
    const float* enc_b2  = (const float*)d_in[4];
    const float* qparams = (const float*)d_in[5];
    const float* dec_w1  = (const float*)d_in[6];
    const float* dec_b1  = (const float*)d_in[7];
    const float* dec_w2  = (const float*)d_in[8];
    const float* dec_b2  = (const float*)d_in[9];
    const float* val_w1  = (const float*)d_in[10];
    const float* val_b1  = (const float*)d_in[11];
    const float* val_w2  = (const float*)d_in[12];
    const float* val_b2  = (const float*)d_in[13];
    float* out = (float*)d_out;

    const int enc_smem = ENC_SMEM_FLOATS * (int)sizeof(float);
    cudaFuncSetAttribute(encoder_kernel, cudaFuncAttributeMaxDynamicSharedMemorySize, enc_smem);

    setup_kernel<<<1, 256>>>(qparams);
    encoder_kernel<<<128, 256, enc_smem>>>(state, enc_w1, enc_b1, enc_w2, enc_b2);
    p1_kernel<<<256, 256>>>();
    low_kernel<<<64, 512>>>(1, 0);
    high_kernel<<<64, 512>>>(1);
    low_kernel<<<64, 512>>>(2, 1);
    high_kernel<<<64, 512>>>(2);
    e2_kernel<<<256, 256>>>();
    gemv_kernel<<<1024, 256>>>(dec_w1, val_w1);
    final_kernel<<<1, 1024>>>(dec_b1, dec_w2, dec_b2, val_b1, val_w2, val_b2, out, out_size);
}

// round 16
// speedup vs baseline: 1.1127x; 1.1127x over previous
#include <cuda_runtime.h>
#include <cstdint>

#define NQ      18
#define QDIM    262144          // 2^18
#define QMASK   (QDIM - 1)
#define XN      73728           // 4096 * 18

// ---------------- device scratch (no allocations allowed) ----------------
__device__ float2 g_gates[54 * 4];   // [layer*18+q][4] = U00,U01,U10,U11
__device__ float2 g_Phi[512];        // layer-0 product-state prefix tables
__device__ float2 g_Plo[512];
__device__ float2 g_xc[XN];
__device__ float2 g_svA[QDIM];
__device__ float2 g_svB[QDIM];
__device__ float  g_acc[132];        // [0..63] dec hid, [64..127] val hid, [128] xnorm2, [129] svnorm2

__device__ __forceinline__ float2 cmul(float2 a, float2 b) {
    return make_float2(a.x * b.x - a.y * b.y, a.x * b.y + a.y * b.x);
}

__device__ __forceinline__ unsigned perm18(unsigned y) {
    return (y ^ (y << 1)) & QMASK;    // composed CNOT-ladder permutation (gather index)
}

// padded smem indexing: kills the 32-way conflicts of the strided butterfly
#define PHYS(l) ((l) + ((l) >> 4))

// apply 2x2 gate u to register pairs differing in bit K of the 16-register block
template <int K>
__device__ __forceinline__ void apply_gate(float2* r, const float2* u) {
    float2 u00 = u[0], u01 = u[1], u10 = u[2], u11 = u[3];
#pragma unroll
    for (int m = 0; m < 16; m++) {
        if (m & (1 << K)) continue;
        float2 v0 = r[m], v1 = r[m | (1 << K)];
        float2 a, b2;
        a.x  = u00.x * v0.x - u00.y * v0.y + u01.x * v1.x - u01.y * v1.y;
        a.y  = u00.x * v0.y + u00.y * v0.x + u01.x * v1.y + u01.y * v1.x;
        b2.x = u10.x * v0.x - u10.y * v0.y + u11.x * v1.x - u11.y * v1.y;
        b2.y = u10.x * v0.y + u10.y * v0.x + u11.x * v1.y + u11.y * v1.x;
        r[m] = a;
        r[m | (1 << K)] = b2;
    }
}

// ---------------- setup: fused gates + layer-0 product tables + zero acc ----------------
__global__ void setup_kernel(const float* __restrict__ qp) {
    __shared__ float2 u0[36];    // col-0 entries of layer-0 gates
    int t = threadIdx.x;
    if (t < 132) g_acc[t] = 0.f;
    if (t < 54) {
        float a = qp[t * 3 + 0] * 0.5f;
        float b = qp[t * 3 + 1] * 0.5f;
        float c = qp[t * 3 + 2] * 0.5f;
        float ca = cosf(a), sa = sinf(a);
        float cb = cosf(b), sb = sinf(b);
        float cc = cosf(c), sc = sinf(c);
        float2 m00 = make_float2( cb * ca,  sb * sa);
        float2 m01 = make_float2(-sb * ca, -cb * sa);
        float2 m10 = make_float2( sb * ca, -cb * sa);
        float2 m11 = make_float2( cb * ca, -sb * sa);
        float2 em = make_float2(cc, -sc);
        float2 ep = make_float2(cc,  sc);
        float2 e0 = cmul(em, m00);
        float2 e1 = cmul(em, m01);
        float2 e2 = cmul(ep, m10);
        float2 e3 = cmul(ep, m11);
        g_gates[t * 4 + 0] = e0;
        g_gates[t * 4 + 1] = e1;
        g_gates[t * 4 + 2] = e2;
        g_gates[t * 4 + 3] = e3;
        if (t < 18) { u0[t * 2 + 0] = e0; u0[t * 2 + 1] = e2; }
    }
    __syncthreads();
    for (int h = t; h < 512; h += 256) {
        float2 p = u0[0 * 2 + ((h >> 8) & 1)];
#pragma unroll
        for (int q = 1; q < 9; q++) p = cmul(p, u0[q * 2 + ((h >> (8 - q)) & 1)]);
        g_Phi[h] = p;
        float2 pl = u0[9 * 2 + ((h >> 8) & 1)];
#pragma unroll
        for (int q = 10; q < 18; q++) pl = cmul(pl, u0[q * 2 + ((h >> (17 - q)) & 1)]);
        g_Plo[h] = pl;
    }
}

// ---------------- encoder: 128 blocks x 32 rows, W1 + state in smem ----------------
#define ENC_SMEM_FLOATS (8192 + 16384 + 2048 + 2304 + 1152 + 256)
__global__ void encoder_kernel(const float* __restrict__ state,
                               const float* __restrict__ w1,
                               const float* __restrict__ b1,
                               const float* __restrict__ w2,
                               const float* __restrict__ b2) {
    extern __shared__ float sm[];
    float* stile = sm;
    float* w1s   = sm + 8192;
    float* hid   = sm + 24576;
    float* w2s   = sm + 26624;
    float* encs  = sm + 28928;
    float* red   = sm + 30080;
    int t = threadIdx.x;
    int R0 = blockIdx.x * 32;

    for (int i = t; i < 8192; i += 256)  stile[i] = state[R0 * 256 + i];
    for (int i = t; i < 16384; i += 256) w1s[i] = w1[i];
    for (int i = t; i < 2304; i += 256)  w2s[i] = w2[i];
    __syncthreads();

    int rg = t >> 4, cq = t & 15;
    int r0 = rg * 2, c0 = cq * 4;
    float a00 = 0, a01 = 0, a02 = 0, a03 = 0, a10 = 0, a11 = 0, a12 = 0, a13 = 0;
    const float* s0p = stile + r0 * 256;
    const float* s1p = stile + (r0 + 1) * 256;
#pragma unroll 4
    for (int k = 0; k < 256; k++) {
        float4 w = *(const float4*)&w1s[k * 64 + c0];
        float s0 = s0p[k], s1 = s1p[k];
        a00 += s0 * w.x; a01 += s0 * w.y; a02 += s0 * w.z; a03 += s0 * w.w;
        a10 += s1 * w.x; a11 += s1 * w.y; a12 += s1 * w.z; a13 += s1 * w.w;
    }
    float bv0 = b1[c0], bv1 = b1[c0 + 1], bv2 = b1[c0 + 2], bv3 = b1[c0 + 3];
    hid[r0 * 64 + c0 + 0] = fmaxf(a00 + bv0, 0.f);
    hid[r0 * 64 + c0 + 1] = fmaxf(a01 + bv1, 0.f);
    hid[r0 * 64 + c0 + 2] = fmaxf(a02 + bv2, 0.f);
    hid[r0 * 64 + c0 + 3] = fmaxf(a03 + bv3, 0.f);
    hid[(r0 + 1) * 64 + c0 + 0] = fmaxf(a10 + bv0, 0.f);
    hid[(r0 + 1) * 64 + c0 + 1] = fmaxf(a11 + bv1, 0.f);
    hid[(r0 + 1) * 64 + c0 + 2] = fmaxf(a12 + bv2, 0.f);
    hid[(r0 + 1) * 64 + c0 + 3] = fmaxf(a13 + bv3, 0.f);
    __syncthreads();

    for (int idx = t; idx < 32 * 36; idx += 256) {
        int r = idx / 36, j = idx % 36;
        float acc = b2[j];
        const float* hrow = hid + r * 64;
#pragma unroll 8
        for (int k = 0; k < 64; k++) acc += hrow[k] * w2s[k * 36 + j];
        encs[idx] = acc;
    }
    __syncthreads();

    float loc = 0.f;
    for (int idx = t; idx < 32 * 18; idx += 256) {
        int r = idx / 18, q = idx % 18;
        float amp = encs[r * 36 + q];
        float ph  = encs[r * 36 + 18 + q];
        float sn, cs;
        sincosf(ph, &sn, &cs);
        g_xc[(R0 + r) * 18 + q] = make_float2(amp * cs, amp * sn);
        loc += amp * amp;
    }
    red[t] = loc;
    __syncthreads();
    for (int s = 128; s > 0; s >>= 1) { if (t < s) red[t] += red[t + s]; __syncthreads(); }
    if (t == 0) atomicAdd(&g_acc[128], red[0]);
}

// ---------------- qsim low pass: gates on chunk-local bits 0..10 (qubits 17..7) ------
// 128 blocks x 128 threads, chunk 2048. Register-blocked: 3 ownership configs,
// 2 smem exchanges. init!=0: build state from layer-0 product tables (perm baked in).
// init==0: gather input through the CNOT perm from svA. Output -> svB.
__global__ void __launch_bounds__(128) qsim_low(int layer, int init) {
    __shared__ float2 ch[2176];      // 2048 + padding
    __shared__ float2 sg[44];        // 11 gates
    __shared__ float2 tabs[1024];    // Phi | Plo
    int t = threadIdx.x, b = blockIdx.x;
    int base = b << 11;
    if (t < 44) {
        int gbit = t >> 2, e = t & 3;
        sg[t] = g_gates[(layer * 18 + (17 - gbit)) * 4 + e];
    }
    if (init) {
        for (int i = t; i < 1024; i += 128)
            tabs[i] = (i < 512) ? g_Phi[i] : g_Plo[i - 512];
    }
    __syncthreads();

    float2 r[16];
    if (init) {
#pragma unroll
        for (int j = 0; j < 16; j++) {
            unsigned g = perm18(base + t * 16 + j);
            r[j] = cmul(tabs[g >> 9], tabs[512 + (g & 511)]);
        }
    } else {
#pragma unroll
        for (int j = 0; j < 16; j++)
            r[j] = g_svA[perm18(base + t * 16 + j)];
    }
    // config c0: register bit k <-> local bit k (gates 0..3)
    apply_gate<0>(r, sg + 0 * 4);
    apply_gate<1>(r, sg + 1 * 4);
    apply_gate<2>(r, sg + 2 * 4);
    apply_gate<3>(r, sg + 3 * 4);
#pragma unroll
    for (int j = 0; j < 16; j++) ch[PHYS(t * 16 + j)] = r[j];
    __syncthreads();
    // config c1: l = bits10..8 = t>>4, bits7..4 = j, bits3..0 = t&15  (gates 4..7)
#pragma unroll
    for (int j = 0; j < 16; j++) {
        int l = ((t >> 4) << 8) | (j << 4) | (t & 15);
        r[j] = ch[PHYS(l)];
    }
    apply_gate<0>(r, sg + 4 * 4);
    apply_gate<1>(r, sg + 5 * 4);
    apply_gate<2>(r, sg + 6 * 4);
    apply_gate<3>(r, sg + 7 * 4);
    __syncthreads();
#pragma unroll
    for (int j = 0; j < 16; j++) {
        int l = ((t >> 4) << 8) | (j << 4) | (t & 15);
        ch[PHYS(l)] = r[j];
    }
    __syncthreads();
    // config c2: l = (j<<7)|t — register bit k <-> local bit 7+k (gates 8..10 via k=1..3)
#pragma unroll
    for (int j = 0; j < 16; j++) r[j] = ch[PHYS((j << 7) | t)];
    apply_gate<1>(r, sg + 8 * 4);
    apply_gate<2>(r, sg + 9 * 4);
    apply_gate<3>(r, sg + 10 * 4);
#pragma unroll
    for (int j = 0; j < 16; j++) g_svB[base + ((j << 7) | t)] = r[j];
}

// ---------------- qsim high pass: gates on global bits 11..17 (qubits 6..0) ----------
// 128 blocks (b = global bits 4..10) x 128 threads; chunk = hi7 x lo4 = 2048.
// svB -> svA.
__global__ void __launch_bounds__(128) qsim_high(int layer) {
    __shared__ float2 ch[2176];
    __shared__ float2 sg[28];        // 7 gates: gk -> global bit 11+gk -> qubit 6-gk
    int t = threadIdx.x, b = blockIdx.x;
    if (t < 28) {
        int gk = t >> 2, e = t & 3;
        sg[t] = g_gates[(layer * 18 + (6 - gk)) * 4 + e];
    }
    __syncthreads();

    float2 r[16];
    // c0: l = ((t>>4)<<8)|(j<<4)|(t&15); register bit k <-> local bit 4+k <-> gate gk=k
#pragma unroll
    for (int j = 0; j < 16; j++) {
        int l = ((t >> 4) << 8) | (j << 4) | (t & 15);
        int glob = ((l >> 4) << 11) | (b << 4) | (l & 15);
        r[j] = g_svB[glob];
    }
    apply_gate<0>(r, sg + 0 * 4);
    apply_gate<1>(r, sg + 1 * 4);
    apply_gate<2>(r, sg + 2 * 4);
    apply_gate<3>(r, sg + 3 * 4);
#pragma unroll
    for (int j = 0; j < 16; j++) {
        int l = ((t >> 4) << 8) | (j << 4) | (t & 15);
        ch[PHYS(l)] = r[j];
    }
    __syncthreads();
    // c1: l = (j<<7)|t; register bit k <-> local bit 7+k <-> gate gk=3+k (k=1..3)
#pragma unroll
    for (int j = 0; j < 16; j++) r[j] = ch[PHYS((j << 7) | t)];
    apply_gate<1>(r, sg + 4 * 4);
    apply_gate<2>(r, sg + 5 * 4);
    apply_gate<3>(r, sg + 6 * 4);
#pragma unroll
    for (int j = 0; j < 16; j++) {
        int l = (j << 7) | t;
        int glob = ((l >> 4) << 11) | (b << 4) | (l & 15);
        g_svA[glob] = r[j];
    }
}

// ---------------- GEMV with fused epilogue: final perm + x-inject + norm -------------
// cl(524288) x [dec_w1 | val_w1]; 1024 blocks x 256 threads, 512 rows each.
__global__ void gemv_kernel(const float* __restrict__ Wd, const float* __restrict__ Wv) {
    __shared__ float cls[512];
    __shared__ float sred[256 * 8];
    int t = threadIdx.x, b = blockIdx.x;
    int j0 = b * 512;
    bool realhalf = (j0 < QDIM);
    float xn2 = g_acc[128];
    float rs = xn2 > 0.f ? rsqrtf(xn2) : 0.f;
    float nloc = 0.f;
    for (int i = t; i < 512; i += 256) {
        int j = j0 + i;
        unsigned y = realhalf ? (unsigned)j : (unsigned)(j - QDIM);
        float2 v = g_svA[perm18(y)];
        if (y < XN) {
            float2 x = g_xc[y];
            v.x += x.x * rs;
            v.y += x.y * rs;
        }
        cls[i] = realhalf ? v.x : v.y;
        if (realhalf) nloc += v.x * v.x + v.y * v.y;
    }
    if (realhalf) {
        for (int o = 16; o; o >>= 1) nloc += __shfl_xor_sync(0xffffffff, nloc, o);
        if ((t & 31) == 0) atomicAdd(&g_acc[129], nloc);
    }
    __syncthreads();

    int rg = t >> 4, cq = t & 15;
    float ad0 = 0, ad1 = 0, ad2 = 0, ad3 = 0;
    float av0 = 0, av1 = 0, av2 = 0, av3 = 0;
#pragma unroll 8
    for (int it = 0; it < 32; it++) {
        int jl = it * 16 + rg;
        float c = cls[jl];
        size_t off = (size_t)(j0 + jl) * 64 + (cq << 2);
        float4 d = __ldg((const float4*)(Wd + off));
        float4 v = __ldg((const float4*)(Wv + off));
        ad0 += c * d.x; ad1 += c * d.y; ad2 += c * d.z; ad3 += c * d.w;
        av0 += c * v.x; av1 += c * v.y; av2 += c * v.z; av3 += c * v.w;
    }
    float* sp = &sred[t * 8];
    sp[0] = ad0; sp[1] = ad1; sp[2] = ad2; sp[3] = ad3;
    sp[4] = av0; sp[5] = av1; sp[6] = av2; sp[7] = av3;
    __syncthreads();
    if (t < 128) {
        int isval = t >> 6;
        int c = t & 63;
        int quad = c >> 2;
        int lane = (c & 3) + isval * 4;
        float s = 0.f;
#pragma unroll
        for (int g = 0; g < 16; g++) s += sred[(g * 16 + quad) * 8 + lane];
        atomicAdd(&g_acc[t], s);     // t = isval*64 + c exactly
    }
}

// ---------------- final: normalize, MLP heads ----------------
__global__ void final_kernel(const float* __restrict__ db1, const float* __restrict__ dw2,
                             const float* __restrict__ db2, const float* __restrict__ vb1,
                             const float* __restrict__ vw2, const float* __restrict__ vb2,
                             float* __restrict__ out, int out_size) {
    __shared__ float hd[64], hv[64];
    int t = threadIdx.x;                  // 128
    float inv = rsqrtf(g_acc[129]);
    if (t < 64)       hd[t]      = fmaxf(g_acc[t] * inv + db1[t], 0.f);
    else              hv[t - 64] = fmaxf(g_acc[t] * inv + vb1[t - 64], 0.f);
    __syncthreads();
    if (t < 18 && t < out_size) {
        float acc = db2[t];
#pragma unroll 8
        for (int k = 0; k < 64; k++) acc += hd[k] * dw2[k * 18 + t];
        out[t] = acc;
    }
    if (t == 32 && out_size > 18) {
        float acc = vb2[0];
#pragma unroll 8
        for (int k = 0; k < 64; k++) acc += hv[k] * vw2[k];
        out[18] = acc;
    }
}

// ---------------- launch ----------------
extern "C" void kernel_launch(void* const* d_in, const int* in_sizes, int n_in,
                              void* d_out, int out_size) {
    const float* state   = (const float*)d_in[0];
    const float* enc_w1  = (const float*)d_in[1];
    const float* enc_b1  = (const float*)d_in[2];
    const float* enc_w2  = (const float*)d_in[3];
    const float* enc_b2  = (const float*)d_in[4];
    const float* qparams = (const float*)d_in[5];
    const float* dec_w1  = (const float*)d_in[6];
    const float* dec_b1  = (const float*)d_in[7];
    const float* dec_w2  = (const float*)d_in[8];
    const float* dec_b2  = (const float*)d_in[9];
    const float* val_w1  = (const float*)d_in[10];
    const float* val_b1  = (const float*)d_in[11];
    const float* val_w2  = (const float*)d_in[12];
    const float* val_b2  = (const float*)d_in[13];
    float* out = (float*)d_out;

    const int enc_smem = ENC_SMEM_FLOATS * (int)sizeof(float);
    cudaFuncSetAttribute(encoder_kernel, cudaFuncAttributeMaxDynamicSharedMemorySize, enc_smem);

    setup_kernel<<<1, 256>>>(qparams);
    encoder_kernel<<<128, 256, enc_smem>>>(state, enc_w1, enc_b1, enc_w2, enc_b2);
    qsim_low <<<128, 128>>>(1, 1);    // layer-1 rotations (low bits), init from product tables (perm0 baked)
    qsim_high<<<128, 128>>>(1);       // layer-1 rotations (high bits)
    qsim_low <<<128, 128>>>(2, 0);    // perm1 gather + layer-2 rotations (low bits)
    qsim_high<<<128, 128>>>(2);       // layer-2 rotations (high bits)
    gemv_kernel<<<1024, 256>>>(dec_w1, val_w1);   // perm2 + x-inject + norm fused into cls load
    final_kernel<<<1, 128>>>(dec_b1, dec_w2, dec_b2, val_b1, val_w2, val_b2, out, out_size);
}

// round 17
// speedup vs baseline: 1.1997x; 1.0782x over previous
#include <cuda_runtime.h>
#include <cstdint>

#define NQ      18
#define QDIM    262144          // 2^18
#define QMASK   (QDIM - 1)
#define XN      73728           // 4096 * 18

// ---------------- device scratch (no allocations allowed) ----------------
__device__ float2 g_gates[54 * 4];   // [layer*18+q][4] = U00,U01,U10,U11
__device__ float2 g_Phi[512];        // layer-0 product-state prefix tables
__device__ float2 g_Plo[512];
__device__ float2 g_xc[XN];
__device__ float2 g_svA[QDIM];
__device__ float2 g_svB[QDIM];
__device__ float  g_acc[132];        // [0..63] dec hid, [64..127] val hid, [128] xnorm2, [129] svnorm2

__device__ __forceinline__ float2 cmul(float2 a, float2 b) {
    return make_float2(a.x * b.x - a.y * b.y, a.x * b.y + a.y * b.x);
}

__device__ __forceinline__ unsigned perm18(unsigned y) {
    return (y ^ (y << 1)) & QMASK;    // composed CNOT-ladder permutation (gather index)
}

// padded smem indexing
#define PHYS(l) ((l) + ((l) >> 4))

// apply 2x2 gate u to register pairs differing in bit K of the 4-register block
template <int K>
__device__ __forceinline__ void apply_gate4(float2* r, const float2* u) {
    float2 u00 = u[0], u01 = u[1], u10 = u[2], u11 = u[3];
#pragma unroll
    for (int m = 0; m < 4; m++) {
        if (m & (1 << K)) continue;
        float2 v0 = r[m], v1 = r[m | (1 << K)];
        float2 a, b2;
        a.x  = u00.x * v0.x - u00.y * v0.y + u01.x * v1.x - u01.y * v1.y;
        a.y  = u00.x * v0.y + u00.y * v0.x + u01.x * v1.y + u01.y * v1.x;
        b2.x = u10.x * v0.x - u10.y * v0.y + u11.x * v1.x - u11.y * v1.y;
        b2.y = u10.x * v0.y + u10.y * v0.x + u11.x * v1.y + u11.y * v1.x;
        r[m] = a;
        r[m | (1 << K)] = b2;
    }
}

// ---------------- setup: fused gates + layer-0 product tables + zero acc ----------------
__global__ void setup_kernel(const float* __restrict__ qp) {
    __shared__ float2 u0[36];    // col-0 entries of layer-0 gates
    int t = threadIdx.x;
    if (t < 132) g_acc[t] = 0.f;
    if (t < 54) {
        float a = qp[t * 3 + 0] * 0.5f;
        float b = qp[t * 3 + 1] * 0.5f;
        float c = qp[t * 3 + 2] * 0.5f;
        float ca = cosf(a), sa = sinf(a);
        float cb = cosf(b), sb = sinf(b);
        float cc = cosf(c), sc = sinf(c);
        float2 m00 = make_float2( cb * ca,  sb * sa);
        float2 m01 = make_float2(-sb * ca, -cb * sa);
        float2 m10 = make_float2( sb * ca, -cb * sa);
        float2 m11 = make_float2( cb * ca, -sb * sa);
        float2 em = make_float2(cc, -sc);
        float2 ep = make_float2(cc,  sc);
        float2 e0 = cmul(em, m00);
        float2 e1 = cmul(em, m01);
        float2 e2 = cmul(ep, m10);
        float2 e3 = cmul(ep, m11);
        g_gates[t * 4 + 0] = e0;
        g_gates[t * 4 + 1] = e1;
        g_gates[t * 4 + 2] = e2;
        g_gates[t * 4 + 3] = e3;
        if (t < 18) { u0[t * 2 + 0] = e0; u0[t * 2 + 1] = e2; }
    }
    __syncthreads();
    for (int h = t; h < 512; h += 256) {
        float2 p = u0[0 * 2 + ((h >> 8) & 1)];
#pragma unroll
        for (int q = 1; q < 9; q++) p = cmul(p, u0[q * 2 + ((h >> (8 - q)) & 1)]);
        g_Phi[h] = p;
        float2 pl = u0[9 * 2 + ((h >> 8) & 1)];
#pragma unroll
        for (int q = 10; q < 18; q++) pl = cmul(pl, u0[q * 2 + ((h >> (17 - q)) & 1)]);
        g_Plo[h] = pl;
    }
}

// ---------------- encoder: 128 blocks x 32 rows, W1 + state in smem ----------------
#define ENC_SMEM_FLOATS (8192 + 16384 + 2048 + 2304 + 1152 + 256)
__global__ void encoder_kernel(const float* __restrict__ state,
                               const float* __restrict__ w1,
                               const float* __restrict__ b1,
                               const float* __restrict__ w2,
                               const float* __restrict__ b2) {
    extern __shared__ float sm[];
    float* stile = sm;
    float* w1s   = sm + 8192;
    float* hid   = sm + 24576;
    float* w2s   = sm + 26624;
    float* encs  = sm + 28928;
    float* red   = sm + 30080;
    int t = threadIdx.x;
    int R0 = blockIdx.x * 32;

    for (int i = t; i < 8192; i += 256)  stile[i] = state[R0 * 256 + i];
    for (int i = t; i < 16384; i += 256) w1s[i] = w1[i];
    for (int i = t; i < 2304; i += 256)  w2s[i] = w2[i];
    __syncthreads();

    int rg = t >> 4, cq = t & 15;
    int r0 = rg * 2, c0 = cq * 4;
    float a00 = 0, a01 = 0, a02 = 0, a03 = 0, a10 = 0, a11 = 0, a12 = 0, a13 = 0;
    const float* s0p = stile + r0 * 256;
    const float* s1p = stile + (r0 + 1) * 256;
#pragma unroll 4
    for (int k = 0; k < 256; k++) {
        float4 w = *(const float4*)&w1s[k * 64 + c0];
        float s0 = s0p[k], s1 = s1p[k];
        a00 += s0 * w.x; a01 += s0 * w.y; a02 += s0 * w.z; a03 += s0 * w.w;
        a10 += s1 * w.x; a11 += s1 * w.y; a12 += s1 * w.z; a13 += s1 * w.w;
    }
    float bv0 = b1[c0], bv1 = b1[c0 + 1], bv2 = b1[c0 + 2], bv3 = b1[c0 + 3];
    hid[r0 * 64 + c0 + 0] = fmaxf(a00 + bv0, 0.f);
    hid[r0 * 64 + c0 + 1] = fmaxf(a01 + bv1, 0.f);
    hid[r0 * 64 + c0 + 2] = fmaxf(a02 + bv2, 0.f);
    hid[r0 * 64 + c0 + 3] = fmaxf(a03 + bv3, 0.f);
    hid[(r0 + 1) * 64 + c0 + 0] = fmaxf(a10 + bv0, 0.f);
    hid[(r0 + 1) * 64 + c0 + 1] = fmaxf(a11 + bv1, 0.f);
    hid[(r0 + 1) * 64 + c0 + 2] = fmaxf(a12 + bv2, 0.f);
    hid[(r0 + 1) * 64 + c0 + 3] = fmaxf(a13 + bv3, 0.f);
    __syncthreads();

    for (int idx = t; idx < 32 * 36; idx += 256) {
        int r = idx / 36, j = idx % 36;
        float acc = b2[j];
        const float* hrow = hid + r * 64;
#pragma unroll 8
        for (int k = 0; k < 64; k++) acc += hrow[k] * w2s[k * 36 + j];
        encs[idx] = acc;
    }
    __syncthreads();

    float loc = 0.f;
    for (int idx = t; idx < 32 * 18; idx += 256) {
        int r = idx / 18, q = idx % 18;
        float amp = encs[r * 36 + q];
        float ph  = encs[r * 36 + 18 + q];
        float sn, cs;
        sincosf(ph, &sn, &cs);
        g_xc[(R0 + r) * 18 + q] = make_float2(amp * cs, amp * sn);
        loc += amp * amp;
    }
    red[t] = loc;
    __syncthreads();
    for (int s = 128; s > 0; s >>= 1) { if (t < s) red[t] += red[t + s]; __syncthreads(); }
    if (t == 0) atomicAdd(&g_acc[128], red[0]);
}

// ---------------- qsim low pass: gates on chunk-local bits 0..9 (qubits 17..8) ------
// 256 blocks x 256 threads, chunk 1024, 4 float2/thread, 5 configs (2 gates each),
// double-buffered smem exchanges. init!=0: build from product tables (perm0 baked).
// init==0: gather through CNOT perm from svA. Output -> svB.
__global__ void __launch_bounds__(256) qsim_low(int layer, int init) {
    __shared__ float2 buf0[1088], buf1[1088];
    __shared__ float2 sg[40];        // 10 gates, beta=0..9 -> qubit 17-beta
    __shared__ float2 tabs[1024];
    int t = threadIdx.x, b = blockIdx.x;
    int base = b << 10;
    if (t < 40) {
        int beta = t >> 2, e = t & 3;
        sg[t] = g_gates[(layer * 18 + (17 - beta)) * 4 + e];
    }
    if (init) {
        for (int i = t; i < 1024; i += 256)
            tabs[i] = (i < 512) ? g_Phi[i] : g_Plo[i - 512];
    }
    __syncthreads();

    float2 r[4];
    // cfg A: l = (t<<2)|j -> reg bit k <-> local bit k (beta 0,1)
    if (init) {
#pragma unroll
        for (int j = 0; j < 4; j++) {
            unsigned g = perm18(base + ((t << 2) | j));
            r[j] = cmul(tabs[g >> 9], tabs[512 + (g & 511)]);
        }
    } else {
#pragma unroll
        for (int j = 0; j < 4; j++)
            r[j] = g_svA[perm18(base + ((t << 2) | j))];
    }
    apply_gate4<0>(r, sg + 0);
    apply_gate4<1>(r, sg + 4);
#pragma unroll
    for (int j = 0; j < 4; j++) buf0[PHYS((t << 2) | j)] = r[j];
    __syncthreads();
    // cfg B: local bits 2..3 (beta 2,3)
#pragma unroll
    for (int j = 0; j < 4; j++) { int l = ((t >> 2) << 4) | (j << 2) | (t & 3); r[j] = buf0[PHYS(l)]; }
    apply_gate4<0>(r, sg + 8);
    apply_gate4<1>(r, sg + 12);
#pragma unroll
    for (int j = 0; j < 4; j++) { int l = ((t >> 2) << 4) | (j << 2) | (t & 3); buf1[PHYS(l)] = r[j]; }
    __syncthreads();
    // cfg C: local bits 4..5 (beta 4,5)
#pragma unroll
    for (int j = 0; j < 4; j++) { int l = ((t >> 4) << 6) | (j << 4) | (t & 15); r[j] = buf1[PHYS(l)]; }
    apply_gate4<0>(r, sg + 16);
    apply_gate4<1>(r, sg + 20);
#pragma unroll
    for (int j = 0; j < 4; j++) { int l = ((t >> 4) << 6) | (j << 4) | (t & 15); buf0[PHYS(l)] = r[j]; }
    __syncthreads();
    // cfg D: local bits 6..7 (beta 6,7)
#pragma unroll
    for (int j = 0; j < 4; j++) { int l = ((t >> 6) << 8) | (j << 6) | (t & 63); r[j] = buf0[PHYS(l)]; }
    apply_gate4<0>(r, sg + 24);
    apply_gate4<1>(r, sg + 28);
#pragma unroll
    for (int j = 0; j < 4; j++) { int l = ((t >> 6) << 8) | (j << 6) | (t & 63); buf1[PHYS(l)] = r[j]; }
    __syncthreads();
    // cfg E: local bits 8..9 (beta 8,9)
#pragma unroll
    for (int j = 0; j < 4; j++) { int l = (j << 8) | t; r[j] = buf1[PHYS(l)]; }
    apply_gate4<0>(r, sg + 32);
    apply_gate4<1>(r, sg + 36);
#pragma unroll
    for (int j = 0; j < 4; j++) g_svB[base | ((j << 8) | t)] = r[j];
}

// ---------------- qsim high pass: gates on global bits 10..17 (qubits 7..0) ----------
// 256 blocks (b = global bits 2..9) x 256 threads; chunk local = glob{10..17} x glob{0..1}.
// svB -> svA.
__global__ void __launch_bounds__(256) qsim_high(int layer) {
    __shared__ float2 buf0[1088], buf1[1088];
    __shared__ float2 sg[32];        // gk=0..7 -> global bit 10+gk -> qubit 7-gk
    int t = threadIdx.x, b = blockIdx.x;
    if (t < 32) {
        int gk = t >> 2, e = t & 3;
        sg[t] = g_gates[(layer * 18 + (7 - gk)) * 4 + e];
    }
    __syncthreads();

    float2 r[4];
    // cfg A: reg <-> local bits 2..3 (global 10..11, gk 0,1); load from global
#pragma unroll
    for (int j = 0; j < 4; j++) {
        int l = ((t >> 2) << 4) | (j << 2) | (t & 3);
        int glob = ((l >> 2) << 10) | (b << 2) | (l & 3);
        r[j] = g_svB[glob];
    }
    apply_gate4<0>(r, sg + 0);
    apply_gate4<1>(r, sg + 4);
#pragma unroll
    for (int j = 0; j < 4; j++) { int l = ((t >> 2) << 4) | (j << 2) | (t & 3); buf0[PHYS(l)] = r[j]; }
    __syncthreads();
    // cfg B: local bits 4..5 (gk 2,3)
#pragma unroll
    for (int j = 0; j < 4; j++) { int l = ((t >> 4) << 6) | (j << 4) | (t & 15); r[j] = buf0[PHYS(l)]; }
    apply_gate4<0>(r, sg + 8);
    apply_gate4<1>(r, sg + 12);
#pragma unroll
    for (int j = 0; j < 4; j++) { int l = ((t >> 4) << 6) | (j << 4) | (t & 15); buf1[PHYS(l)] = r[j]; }
    __syncthreads();
    // cfg C: local bits 6..7 (gk 4,5)
#pragma unroll
    for (int j = 0; j < 4; j++) { int l = ((t >> 6) << 8) | (j << 6) | (t & 63); r[j] = buf1[PHYS(l)]; }
    apply_gate4<0>(r, sg + 16);
    apply_gate4<1>(r, sg + 20);
#pragma unroll
    for (int j = 0; j < 4; j++) { int l = ((t >> 6) << 8) | (j << 6) | (t & 63); buf0[PHYS(l)] = r[j]; }
    __syncthreads();
    // cfg D: local bits 8..9 (gk 6,7); store to global
#pragma unroll
    for (int j = 0; j < 4; j++) { int l = (j << 8) | t; r[j] = buf0[PHYS(l)]; }
    apply_gate4<0>(r, sg + 24);
    apply_gate4<1>(r, sg + 28);
#pragma unroll
    for (int j = 0; j < 4; j++) {
        int l = (j << 8) | t;
        int glob = ((l >> 2) << 10) | (b << 2) | (l & 3);
        g_svA[glob] = r[j];
    }
}

// ---------------- GEMV with fused epilogue: final perm + x-inject + norm -------------
__global__ void gemv_kernel(const float* __restrict__ Wd, const float* __restrict__ Wv) {
    __shared__ float cls[512];
    __shared__ float sred[256 * 8];
    int t = threadIdx.x, b = blockIdx.x;
    int j0 = b * 512;
    bool realhalf = (j0 < QDIM);
    float xn2 = g_acc[128];
    float rs = xn2 > 0.f ? rsqrtf(xn2) : 0.f;
    float nloc = 0.f;
    for (int i = t; i < 512; i += 256) {
        int j = j0 + i;
        unsigned y = realhalf ? (unsigned)j : (unsigned)(j - QDIM);
        float2 v = g_svA[perm18(y)];
        if (y < XN) {
            float2 x = g_xc[y];
            v.x += x.x * rs;
            v.y += x.y * rs;
        }
        cls[i] = realhalf ? v.x : v.y;
        if (realhalf) nloc += v.x * v.x + v.y * v.y;
    }
    if (realhalf) {
        for (int o = 16; o; o >>= 1) nloc += __shfl_xor_sync(0xffffffff, nloc, o);
        if ((t & 31) == 0) atomicAdd(&g_acc[129], nloc);
    }
    __syncthreads();

    int rg = t >> 4, cq = t & 15;
    float ad0 = 0, ad1 = 0, ad2 = 0, ad3 = 0;
    float av0 = 0, av1 = 0, av2 = 0, av3 = 0;
#pragma unroll 8
    for (int it = 0; it < 32; it++) {
        int jl = it * 16 + rg;
        float c = cls[jl];
        size_t off = (size_t)(j0 + jl) * 64 + (cq << 2);
        float4 d = __ldg((const float4*)(Wd + off));
        float4 v = __ldg((const float4*)(Wv + off));
        ad0 += c * d.x; ad1 += c * d.y; ad2 += c * d.z; ad3 += c * d.w;
        av0 += c * v.x; av1 += c * v.y; av2 += c * v.z; av3 += c * v.w;
    }
    float* sp = &sred[t * 8];
    sp[0] = ad0; sp[1] = ad1; sp[2] = ad2; sp[3] = ad3;
    sp[4] = av0; sp[5] = av1; sp[6] = av2; sp[7] = av3;
    __syncthreads();
    if (t < 128) {
        int isval = t >> 6;
        int c = t & 63;
        int quad = c >> 2;
        int lane = (c & 3) + isval * 4;
        float s = 0.f;
#pragma unroll
        for (int g = 0; g < 16; g++) s += sred[(g * 16 + quad) * 8 + lane];
        atomicAdd(&g_acc[t], s);     // t = isval*64 + c exactly
    }
}

// ---------------- final: normalize, MLP heads ----------------
__global__ void final_kernel(const float* __restrict__ db1, const float* __restrict__ dw2,
                             const float* __restrict__ db2, const float* __restrict__ vb1,
                             const float* __restrict__ vw2, const float* __restrict__ vb2,
                             float* __restrict__ out, int out_size) {
    __shared__ float hd[64], hv[64];
    int t = threadIdx.x;                  // 128
    float inv = rsqrtf(g_acc[129]);
    if (t < 64)       hd[t]      = fmaxf(g_acc[t] * inv + db1[t], 0.f);
    else              hv[t - 64] = fmaxf(g_acc[t] * inv + vb1[t - 64], 0.f);
    __syncthreads();
    if (t < 18 && t < out_size) {
        float acc = db2[t];
#pragma unroll 8
        for (int k = 0; k < 64; k++) acc += hd[k] * dw2[k * 18 + t];
        out[t] = acc;
    }
    if (t == 32 && out_size > 18) {
        float acc = vb2[0];
#pragma unroll 8
        for (int k = 0; k < 64; k++) acc += hv[k] * vw2[k];
        out[18] = acc;
    }
}

// ---------------- stream fork resources (host-side only; no device mem) ----------------
struct AuxStreams {
    cudaStream_t s2 = 0;
    cudaEvent_t evFork = 0, evJoin = 0;
    bool ok = false;
    AuxStreams() {
        if (cudaStreamCreateWithFlags(&s2, cudaStreamNonBlocking) == cudaSuccess &&
            cudaEventCreateWithFlags(&evFork, cudaEventDisableTiming) == cudaSuccess &&
            cudaEventCreateWithFlags(&evJoin, cudaEventDisableTiming) == cudaSuccess) {
            ok = true;
        } else {
            s2 = 0;
            ok = false;
        }
    }
};
static AuxStreams g_aux;

// ---------------- launch ----------------
extern "C" void kernel_launch(void* const* d_in, const int* in_sizes, int n_in,
                              void* d_out, int out_size) {
    const float* state   = (const float*)d_in[0];
    const float* enc_w1  = (const float*)d_in[1];
    const float* enc_b1  = (const float*)d_in[2];
    const float* enc_w2  = (const float*)d_in[3];
    const float* enc_b2  = (const float*)d_in[4];
    const float* qparams = (const float*)d_in[5];
    const float* dec_w1  = (const float*)d_in[6];
    const float* dec_b1  = (const float*)d_in[7];
    const float* dec_w2  = (const float*)d_in[8];
    const float* dec_b2  = (const float*)d_in[9];
    const float* val_w1  = (const float*)d_in[10];
    const float* val_b1  = (const float*)d_in[11];
    const float* val_w2  = (const float*)d_in[12];
    const float* val_b2  = (const float*)d_in[13];
    float* out = (float*)d_out;

    const int enc_smem = ENC_SMEM_FLOATS * (int)sizeof(float);
    cudaFuncSetAttribute(encoder_kernel, cudaFuncAttributeMaxDynamicSharedMemorySize, enc_smem);

    setup_kernel<<<1, 256>>>(qparams);

    if (g_aux.ok) {
        // fork: encoder (independent of qsim until gemv) runs concurrently
        cudaEventRecord(g_aux.evFork, 0);
        cudaStreamWaitEvent(g_aux.s2, g_aux.evFork, 0);
        encoder_kernel<<<128, 256, enc_smem, g_aux.s2>>>(state, enc_w1, enc_b1, enc_w2, enc_b2);
        cudaEventRecord(g_aux.evJoin, g_aux.s2);
    } else {
        encoder_kernel<<<128, 256, enc_smem>>>(state, enc_w1, enc_b1, enc_w2, enc_b2);
    }

    qsim_low <<<256, 256>>>(1, 1);    // layer-1 rotations (low bits), init from product tables (perm0 baked)
    qsim_high<<<256, 256>>>(1);       // layer-1 rotations (high bits)
    qsim_low <<<256, 256>>>(2, 0);    // perm1 gather + layer-2 rotations (low bits)
    qsim_high<<<256, 256>>>(2);       // layer-2 rotations (high bits)

    if (g_aux.ok) cudaStreamWaitEvent(0, g_aux.evJoin, 0);   // join before gemv

    gemv_kernel<<<1024, 256>>>(dec_w1, val_w1);   // perm2 + x-inject + norm fused into cls load
    final_kernel<<<1, 128>>>(dec_b1, dec_w2, dec_b2, val_b1, val_w2, val_b2, out, out_size);
}